// round 15
// baseline (speedup 1.0000x reference)
#include <cuda_runtime.h>
#include <cuda_fp16.h>
#include <cstdint>
#include <cstddef>

#define DEVI __device__ __forceinline__

static constexpr int M_DIM = 8192;
static constexpr int N_DIM = 4096;
static constexpr int K_DIM = 4096;

static constexpr int BM = 256;
static constexpr int BN = 128;
static constexpr int BK = 128;              // 128 halves = 256B smem rows
static constexpr int NTHREADS = 256;        // 8 warps: 4 in M x 2 in N, warp tile 64x64
static constexpr int NKITER = K_DIM / BK;   // 32
static constexpr int NTILES = (M_DIM / BM) * (N_DIM / BN);  // 1024
static constexpr int GRID_SMS = 148;        // persistent CTAs

static constexpr int A_STAGE_BYTES = BM * BK * 2;   // 65536
static constexpr int B_STAGE_BYTES = BN * BK * 2;   // 32768
static constexpr int STAGE_BYTES = A_STAGE_BYTES + B_STAGE_BYTES;  // 98304
static constexpr int SMEM_TOTAL = 2 * STAGE_BYTES;                 // 196608

// Scratch: x in fp16, W quantized*127 (exact integer in fp16) transposed to [N,K],
// bias pre-quantized to fp32.
__device__ __half g_xh[(size_t)M_DIM * K_DIM];
__device__ __half g_wt[(size_t)N_DIM * K_DIM];
__device__ float  g_bq[N_DIM];

// ---------------- helpers ----------------
DEVI uint32_t smem_u32(const void* p) {
    uint32_t a;
    asm("{ .reg .u64 t; cvta.to.shared.u64 t, %1; cvt.u32.u64 %0, t; }" : "=r"(a) : "l"(p));
    return a;
}

#define CPA16(dst, src) \
    asm volatile("cp.async.cg.shared.global [%0], [%1], 16;" :: "r"(dst), "l"(src) : "memory")
#define CPA_COMMIT() asm volatile("cp.async.commit_group;" ::: "memory")
#define CPA_WAIT(n)  asm volatile("cp.async.wait_group %0;" :: "n"(n) : "memory")

#define LDSM4(r, addr) \
    asm volatile("ldmatrix.sync.aligned.m8n8.x4.shared.b16 {%0,%1,%2,%3}, [%4];" \
        : "=r"((r)[0]), "=r"((r)[1]), "=r"((r)[2]), "=r"((r)[3]) : "r"(addr))

DEVI void mma16816(float* c, const uint32_t* a, uint32_t b0, uint32_t b1) {
    asm volatile(
        "mma.sync.aligned.m16n8k16.row.col.f32.f16.f16.f32 "
        "{%0,%1,%2,%3}, {%4,%5,%6,%7}, {%8,%9}, {%0,%1,%2,%3};"
        : "+f"(c[0]), "+f"(c[1]), "+f"(c[2]), "+f"(c[3])
        : "r"(a[0]), "r"(a[1]), "r"(a[2]), "r"(a[3]), "r"(b0), "r"(b1));
}

// ---------------- fused preprocessing ----------------
// Blocks [0, XBLKS): x fp32->fp16.
// Blocks [XBLKS, XBLKS+WBLKS): W quantize+transpose.
// Blocks [XBLKS+WBLKS, +BBLKS): bias quantize.
static constexpr int XBLKS = (int)(((size_t)M_DIM * K_DIM) / (256 * 8));  // 16384
static constexpr int WBLKS = (N_DIM / 64) * (K_DIM / 64);                 // 4096
static constexpr int BBLKS = N_DIM / (256 * 8);                           // 2

__global__ void __launch_bounds__(256) prep_kernel(
    const float* __restrict__ X, const float* __restrict__ W,
    const float* __restrict__ B) {
    __shared__ __half tile[64][66];
    int bx = blockIdx.x;
    int t = threadIdx.x;

    if (bx < XBLKS) {
        size_t i = ((size_t)bx * 256 + t) * 8;
        float4 a = *reinterpret_cast<const float4*>(X + i);
        float4 b = *reinterpret_cast<const float4*>(X + i + 4);
        __half2 p0 = __floats2half2_rn(a.x, a.y);
        __half2 p1 = __floats2half2_rn(a.z, a.w);
        __half2 p2 = __floats2half2_rn(b.x, b.y);
        __half2 p3 = __floats2half2_rn(b.z, b.w);
        uint4 u;
        u.x = *reinterpret_cast<uint32_t*>(&p0);
        u.y = *reinterpret_cast<uint32_t*>(&p1);
        u.z = *reinterpret_cast<uint32_t*>(&p2);
        u.w = *reinterpret_cast<uint32_t*>(&p3);
        *reinterpret_cast<uint4*>(g_xh + i) = u;
    } else if (bx < XBLKS + WBLKS) {
        int wb = bx - XBLKS;
        int n0 = (wb & 63) * 64;
        int k0 = (wb >> 6) * 64;
        int r = t >> 6;
        int c = t & 63;
#pragma unroll
        for (int rr = 0; rr < 16; rr++) {
            int k = r + rr * 4;
            float w = W[(size_t)(k0 + k) * N_DIM + n0 + c];
            w = fminf(fmaxf(w, -1.0f), 1.0f);
            tile[k][c] = __float2half_rn(rintf(w * 127.0f));
        }
        __syncthreads();
#pragma unroll
        for (int ww = 0; ww < 16; ww++) {
            int nl = r + ww * 4;
            g_wt[(size_t)(n0 + nl) * K_DIM + k0 + c] = tile[c][nl];
        }
    } else {
        int i0 = (bx - XBLKS - WBLKS) * 2048 + t * 8;
        const float inv127 = 1.0f / 127.0f;
#pragma unroll
        for (int j = 0; j < 8; j++) {
            float b = B[i0 + j];
            b = fminf(fmaxf(b, -1.0f), 1.0f);
            g_bq[i0 + j] = rintf(b * 127.0f) * inv127;
        }
    }
}

// ---------------- GEMM ----------------

// 256B rows, 16 chunks of 16B; chunk swizzle c ^ (r&7).
DEVI void pieceA(uint32_t sA, const __half* __restrict__ a, int tid, int i) {
    int id = tid + i * NTHREADS;
    int r = id >> 4;
    int c = id & 15;
    CPA16(sA + (uint32_t)(r * 256 + ((c ^ (r & 7)) << 4)), a + (size_t)r * K_DIM + c * 8);
}
DEVI void pieceB(uint32_t sB, const __half* __restrict__ b, int tid, int i) {
    int id = tid + i * NTHREADS;
    int r = id >> 4;
    int c = id & 15;
    CPA16(sB + (uint32_t)(r * 256 + ((c ^ (r & 7)) << 4)), b + (size_t)r * K_DIM + c * 8);
}

__global__ void __launch_bounds__(NTHREADS, 1) pwb_gemm_kernel(
    float* __restrict__ out) {
    extern __shared__ char smem[];
    uint32_t sbase = smem_u32(smem);

    int tid = threadIdx.x;
    int lane = tid & 31;
    int w = tid >> 5;                 // 0..7
    int warp_m = (w >> 1) * 64;       // 4 warps in M
    int warp_n = (w & 1) * 64;        // 2 warps in N

    // ldmatrix address components (chunk-XOR swizzle, 256B rows)
    uint32_t aBase = (uint32_t)(warp_m + (lane & 15)) * 256;                      // + mi*4096
    uint32_t bBase = (uint32_t)(warp_n + ((lane >> 4) << 3) + (lane & 7)) * 256;  // + g*4096
    uint32_t swzA[8], swzB[8];
#pragma unroll
    for (int ks = 0; ks < 8; ks++) {
        swzA[ks] = (uint32_t)(((ks * 2 + (lane >> 4)) ^ (lane & 7)) << 4);
        swzB[ks] = (uint32_t)(((ks * 2 + ((lane >> 3) & 1)) ^ (lane & 7)) << 4);
    }

    uint32_t afr[2][4][4];
    uint32_t bfr[2][4][4];
    float acc[4][8][4];

    int tile = blockIdx.x;            // persistent: tile += GRID_SMS
    const __half* gA = g_xh + (size_t)(tile >> 5) * BM * K_DIM;
    const __half* gB = g_wt + (size_t)(tile & 31) * BN * K_DIM;

    // prologue: load first tile's stage0 into buffer 0, then ks0 fragments
    {
        uint32_t sA = sbase;
        uint32_t sB = sbase + A_STAGE_BYTES;
#pragma unroll
        for (int i = 0; i < 16; i++) pieceA(sA, gA, tid, i);
#pragma unroll
        for (int i = 0; i < 8; i++) pieceB(sB, gB, tid, i);
        CPA_COMMIT();
        CPA_WAIT(0);
        __syncthreads();
#pragma unroll
        for (int mi = 0; mi < 4; mi++)
            LDSM4(afr[0][mi], sA + aBase + mi * 4096 + swzA[0]);
#pragma unroll
        for (int g = 0; g < 4; g++)
            LDSM4(bfr[0][g], sB + bBase + g * 4096 + swzB[0]);
    }

    int buf = 0;
    while (true) {
        int nextTile = tile + GRID_SMS;
        const __half* nA = g_xh + (size_t)(nextTile >> 5) * BM * K_DIM;
        const __half* nB = g_wt + (size_t)(nextTile & 31) * BN * K_DIM;
        bool haveNext = (nextTile < NTILES);

#pragma unroll
        for (int mi = 0; mi < 4; mi++)
#pragma unroll
            for (int nj = 0; nj < 8; nj++)
#pragma unroll
                for (int e = 0; e < 4; e++) acc[mi][nj][e] = 0.0f;

        for (int it = 0; it < NKITER; it++) {
            uint32_t sA = sbase + buf * STAGE_BYTES;
            uint32_t sB = sA + A_STAGE_BYTES;
            uint32_t pA = sbase + (buf ^ 1) * STAGE_BYTES;
            uint32_t pB = pA + A_STAGE_BYTES;

            // prefetch target: next K-stage of this tile, or next tile's stage 0
            bool last = (it == NKITER - 1);
            bool pf = !last || haveNext;
            const __half* pa = last ? nA : (gA + (it + 1) * BK);
            const __half* pb = last ? nB : (gB + (it + 1) * BK);

#pragma unroll
            for (int ks = 0; ks < 8; ks++) {
                int cur = ks & 1, nxt = cur ^ 1;

                // fragment prefetch for ks+1 (current stage)
                if (ks < 7) {
#pragma unroll
                    for (int mi = 0; mi < 4; mi++)
                        LDSM4(afr[nxt][mi], sA + aBase + mi * 4096 + swzA[ks + 1]);
#pragma unroll
                    for (int g = 0; g < 4; g++)
                        LDSM4(bfr[nxt][g], sB + bBase + g * 4096 + swzB[ks + 1]);
                }

                // next-stage global prefetch: spread issue ks0-2, commit ks2
                if (pf) {
                    if (ks == 0) {
#pragma unroll
                        for (int i = 0; i < 8; i++) pieceA(pA, pa, tid, i);
                    }
                    if (ks == 1) {
#pragma unroll
                        for (int i = 8; i < 16; i++) pieceA(pA, pa, tid, i);
                    }
                    if (ks == 2) {
#pragma unroll
                        for (int i = 0; i < 8; i++) pieceB(pB, pb, tid, i);
                        CPA_COMMIT();
                    }
                    // next stage resident + all reads of current stage done:
                    // barrier covered by ks6/ks7 MMA work
                    if (ks == 6) {
                        CPA_WAIT(0);
                        __syncthreads();
                    }
                    // load ks0 fragments of NEXT stage, overlapping ks7 MMAs
                    if (ks == 7) {
#pragma unroll
                        for (int mi = 0; mi < 4; mi++)
                            LDSM4(afr[0][mi], pA + aBase + mi * 4096 + swzA[0]);
#pragma unroll
                        for (int g = 0; g < 4; g++)
                            LDSM4(bfr[0][g], pB + bBase + g * 4096 + swzB[0]);
                    }
                }

#pragma unroll
                for (int mi = 0; mi < 4; mi++) {
#pragma unroll
                    for (int nj = 0; nj < 8; nj++) {
                        mma16816(acc[mi][nj], afr[cur][mi],
                                 bfr[cur][nj >> 1][(nj & 1) * 2],
                                 bfr[cur][nj >> 1][(nj & 1) * 2 + 1]);
                    }
                }
            }
            buf ^= 1;
        }

        // ---------------- epilogue: scale + pre-quantized bias + relu ----------------
        // (next tile's stage0 is already loaded; its ks0 fragments are in slot 0)
        {
            int ctaM = (tile >> 5) * BM;
            int ctaN = (tile & 31) * BN;
            const float inv127 = 1.0f / 127.0f;
            int grow0 = ctaM + warp_m + (lane >> 2);
            int gcol0 = ctaN + warp_n + (lane & 3) * 2;

            float2 bq[8];
#pragma unroll
            for (int nj = 0; nj < 8; nj++)
                bq[nj] = *reinterpret_cast<const float2*>(g_bq + gcol0 + nj * 8);

#pragma unroll
            for (int mi = 0; mi < 4; mi++) {
#pragma unroll
                for (int h = 0; h < 2; h++) {
                    int grow = grow0 + mi * 16 + h * 8;
                    float* orow = out + (size_t)grow * N_DIM;
#pragma unroll
                    for (int nj = 0; nj < 8; nj++) {
                        float2 v;
                        v.x = fmaxf(fmaf(acc[mi][nj][h * 2 + 0], inv127, bq[nj].x), 0.0f);
                        v.y = fmaxf(fmaf(acc[mi][nj][h * 2 + 1], inv127, bq[nj].y), 0.0f);
                        *reinterpret_cast<float2*>(orow + gcol0 + nj * 8) = v;
                    }
                }
            }
        }

        if (!haveNext) break;
        tile = nextTile;
        gA = nA;
        gB = nB;
    }
}

// ---------------- launch ----------------
extern "C" void kernel_launch(void* const* d_in, const int* in_sizes, int n_in,
                              void* d_out, int out_size) {
    const float* x = (const float*)d_in[0];
    const float* w = (const float*)d_in[1];
    const float* bias = (const float*)d_in[2];
    float* out = (float*)d_out;

    cudaFuncSetAttribute(pwb_gemm_kernel,
                         cudaFuncAttributeMaxDynamicSharedMemorySize, SMEM_TOTAL);

    prep_kernel<<<XBLKS + WBLKS + BBLKS, 256>>>(x, w, bias);
    pwb_gemm_kernel<<<GRID_SMS, NTHREADS, SMEM_TOTAL>>>(out);
}

// round 16
// speedup vs baseline: 1.5207x; 1.5207x over previous
#include <cuda_runtime.h>
#include <cuda_fp16.h>
#include <cstdint>
#include <cstddef>

#define DEVI __device__ __forceinline__

static constexpr int M_DIM = 8192;
static constexpr int N_DIM = 4096;
static constexpr int K_DIM = 4096;

static constexpr int BM = 256;
static constexpr int BN = 128;
static constexpr int BK = 128;              // 128 halves = 256B smem rows
static constexpr int NTHREADS = 256;        // 8 warps: 4 in M x 2 in N, warp tile 64x64
static constexpr int NKITER = K_DIM / BK;   // 32
static constexpr int NTILES = (M_DIM / BM) * (N_DIM / BN);  // 1024
static constexpr int GRID_SMS = 148;        // persistent CTAs

static constexpr int A_STAGE_BYTES = BM * BK * 2;   // 65536
static constexpr int B_STAGE_BYTES = BN * BK * 2;   // 32768
static constexpr int STAGE_BYTES = A_STAGE_BYTES + B_STAGE_BYTES;  // 98304
static constexpr int SMEM_TOTAL = 2 * STAGE_BYTES;                 // 196608

// Scratch: x in fp16, W quantized*127 (exact integer in fp16) transposed to [N,K],
// bias pre-quantized to fp32.
__device__ __half g_xh[(size_t)M_DIM * K_DIM];
__device__ __half g_wt[(size_t)N_DIM * K_DIM];
__device__ float  g_bq[N_DIM];

// ---------------- helpers ----------------
DEVI uint32_t smem_u32(const void* p) {
    uint32_t a;
    asm("{ .reg .u64 t; cvta.to.shared.u64 t, %1; cvt.u32.u64 %0, t; }" : "=r"(a) : "l"(p));
    return a;
}

#define CPA16(dst, src) \
    asm volatile("cp.async.cg.shared.global [%0], [%1], 16;" :: "r"(dst), "l"(src) : "memory")
#define CPA_COMMIT() asm volatile("cp.async.commit_group;" ::: "memory")
#define CPA_WAIT(n)  asm volatile("cp.async.wait_group %0;" :: "n"(n) : "memory")

#define LDSM4(r, addr) \
    asm volatile("ldmatrix.sync.aligned.m8n8.x4.shared.b16 {%0,%1,%2,%3}, [%4];" \
        : "=r"((r)[0]), "=r"((r)[1]), "=r"((r)[2]), "=r"((r)[3]) : "r"(addr))

DEVI void mma16816(float* c, const uint32_t* a, uint32_t b0, uint32_t b1) {
    asm volatile(
        "mma.sync.aligned.m16n8k16.row.col.f32.f16.f16.f32 "
        "{%0,%1,%2,%3}, {%4,%5,%6,%7}, {%8,%9}, {%0,%1,%2,%3};"
        : "+f"(c[0]), "+f"(c[1]), "+f"(c[2]), "+f"(c[3])
        : "r"(a[0]), "r"(a[1]), "r"(a[2]), "r"(a[3]), "r"(b0), "r"(b1));
}

// ---------------- fused preprocessing ----------------
// Blocks [0, XBLKS): x fp32->fp16.
// Blocks [XBLKS, XBLKS+WBLKS): W quantize+transpose.
// Blocks [XBLKS+WBLKS, +BBLKS): bias quantize.
static constexpr int XBLKS = (int)(((size_t)M_DIM * K_DIM) / (256 * 8));  // 16384
static constexpr int WBLKS = (N_DIM / 64) * (K_DIM / 64);                 // 4096
static constexpr int BBLKS = N_DIM / (256 * 8);                           // 2

__global__ void __launch_bounds__(256) prep_kernel(
    const float* __restrict__ X, const float* __restrict__ W,
    const float* __restrict__ B) {
    __shared__ __half tile[64][66];
    int bx = blockIdx.x;
    int t = threadIdx.x;

    if (bx < XBLKS) {
        size_t i = ((size_t)bx * 256 + t) * 8;
        float4 a = *reinterpret_cast<const float4*>(X + i);
        float4 b = *reinterpret_cast<const float4*>(X + i + 4);
        __half2 p0 = __floats2half2_rn(a.x, a.y);
        __half2 p1 = __floats2half2_rn(a.z, a.w);
        __half2 p2 = __floats2half2_rn(b.x, b.y);
        __half2 p3 = __floats2half2_rn(b.z, b.w);
        uint4 u;
        u.x = *reinterpret_cast<uint32_t*>(&p0);
        u.y = *reinterpret_cast<uint32_t*>(&p1);
        u.z = *reinterpret_cast<uint32_t*>(&p2);
        u.w = *reinterpret_cast<uint32_t*>(&p3);
        *reinterpret_cast<uint4*>(g_xh + i) = u;
    } else if (bx < XBLKS + WBLKS) {
        int wb = bx - XBLKS;
        int n0 = (wb & 63) * 64;
        int k0 = (wb >> 6) * 64;
        int r = t >> 6;
        int c = t & 63;
#pragma unroll
        for (int rr = 0; rr < 16; rr++) {
            int k = r + rr * 4;
            float w = W[(size_t)(k0 + k) * N_DIM + n0 + c];
            w = fminf(fmaxf(w, -1.0f), 1.0f);
            tile[k][c] = __float2half_rn(rintf(w * 127.0f));
        }
        __syncthreads();
#pragma unroll
        for (int ww = 0; ww < 16; ww++) {
            int nl = r + ww * 4;
            g_wt[(size_t)(n0 + nl) * K_DIM + k0 + c] = tile[c][nl];
        }
    } else {
        int i0 = (bx - XBLKS - WBLKS) * 2048 + t * 8;
        const float inv127 = 1.0f / 127.0f;
#pragma unroll
        for (int j = 0; j < 8; j++) {
            float b = B[i0 + j];
            b = fminf(fmaxf(b, -1.0f), 1.0f);
            g_bq[i0 + j] = rintf(b * 127.0f) * inv127;
        }
    }
}

// ---------------- GEMM ----------------

// 256B rows, 16 chunks of 16B; chunk swizzle c ^ (r&7).
DEVI void pieceA(uint32_t sA, const __half* __restrict__ a, int tid, int i) {
    int id = tid + i * NTHREADS;
    int r = id >> 4;
    int c = id & 15;
    CPA16(sA + (uint32_t)(r * 256 + ((c ^ (r & 7)) << 4)), a + (size_t)r * K_DIM + c * 8);
}
DEVI void pieceB(uint32_t sB, const __half* __restrict__ b, int tid, int i) {
    int id = tid + i * NTHREADS;
    int r = id >> 4;
    int c = id & 15;
    CPA16(sB + (uint32_t)(r * 256 + ((c ^ (r & 7)) << 4)), b + (size_t)r * K_DIM + c * 8);
}

__global__ void __launch_bounds__(NTHREADS, 1) pwb_gemm_kernel(
    float* __restrict__ out) {
    extern __shared__ char smem[];
    uint32_t sbase = smem_u32(smem);

    int tid = threadIdx.x;
    int lane = tid & 31;
    int w = tid >> 5;                 // 0..7
    int warp_m = (w >> 1) * 64;       // 4 warps in M
    int warp_n = (w & 1) * 64;        // 2 warps in N

    // ldmatrix address components (chunk-XOR swizzle, 256B rows)
    uint32_t aBase = (uint32_t)(warp_m + (lane & 15)) * 256;                      // + mi*4096
    uint32_t bBase = (uint32_t)(warp_n + ((lane >> 4) << 3) + (lane & 7)) * 256;  // + g*4096
    uint32_t swzA[8], swzB[8];
#pragma unroll
    for (int ks = 0; ks < 8; ks++) {
        swzA[ks] = (uint32_t)(((ks * 2 + (lane >> 4)) ^ (lane & 7)) << 4);
        swzB[ks] = (uint32_t)(((ks * 2 + ((lane >> 3) & 1)) ^ (lane & 7)) << 4);
    }

    uint32_t afr[2][4][4];
    uint32_t bfr[2][4][4];
    float acc[4][8][4];

    int tile = blockIdx.x;            // persistent: tile += GRID_SMS
    const __half* gA = g_xh + (size_t)(tile >> 5) * BM * K_DIM;
    const __half* gB = g_wt + (size_t)(tile & 31) * BN * K_DIM;

    // prologue: load first tile's stage0 into buffer 0, then ks0 fragments
    {
        uint32_t sA = sbase;
        uint32_t sB = sbase + A_STAGE_BYTES;
#pragma unroll
        for (int i = 0; i < 16; i++) pieceA(sA, gA, tid, i);
#pragma unroll
        for (int i = 0; i < 8; i++) pieceB(sB, gB, tid, i);
        CPA_COMMIT();
        CPA_WAIT(0);
        __syncthreads();
#pragma unroll
        for (int mi = 0; mi < 4; mi++)
            LDSM4(afr[0][mi], sA + aBase + mi * 4096 + swzA[0]);
#pragma unroll
        for (int g = 0; g < 4; g++)
            LDSM4(bfr[0][g], sB + bBase + g * 4096 + swzB[0]);
    }

    int buf = 0;
    while (true) {
        int nextTile = tile + GRID_SMS;
        const __half* nA = g_xh + (size_t)(nextTile >> 5) * BM * K_DIM;
        const __half* nB = g_wt + (size_t)(nextTile & 31) * BN * K_DIM;
        bool haveNext = (nextTile < NTILES);

#pragma unroll
        for (int mi = 0; mi < 4; mi++)
#pragma unroll
            for (int nj = 0; nj < 8; nj++)
#pragma unroll
                for (int e = 0; e < 4; e++) acc[mi][nj][e] = 0.0f;

        for (int it = 0; it < NKITER; it++) {
            uint32_t sA = sbase + buf * STAGE_BYTES;
            uint32_t sB = sA + A_STAGE_BYTES;
            uint32_t pA = sbase + (buf ^ 1) * STAGE_BYTES;
            uint32_t pB = pA + A_STAGE_BYTES;

            // prefetch target: next K-stage of this tile, or next tile's stage 0
            bool last = (it == NKITER - 1);
            bool pf = !last || haveNext;
            const __half* pa = last ? nA : (gA + (it + 1) * BK);
            const __half* pb = last ? nB : (gB + (it + 1) * BK);

#pragma unroll
            for (int ks = 0; ks < 8; ks++) {
                int cur = ks & 1, nxt = cur ^ 1;

                // fragment prefetch for ks+1 (current stage)
                if (ks < 7) {
#pragma unroll
                    for (int mi = 0; mi < 4; mi++)
                        LDSM4(afr[nxt][mi], sA + aBase + mi * 4096 + swzA[ks + 1]);
#pragma unroll
                    for (int g = 0; g < 4; g++)
                        LDSM4(bfr[nxt][g], sB + bBase + g * 4096 + swzB[ks + 1]);
                }

                // next-stage global prefetch: spread issue ks0-2, commit ks2
                if (pf) {
                    if (ks == 0) {
#pragma unroll
                        for (int i = 0; i < 8; i++) pieceA(pA, pa, tid, i);
                    }
                    if (ks == 1) {
#pragma unroll
                        for (int i = 8; i < 16; i++) pieceA(pA, pa, tid, i);
                    }
                    if (ks == 2) {
#pragma unroll
                        for (int i = 0; i < 8; i++) pieceB(pB, pb, tid, i);
                        CPA_COMMIT();
                    }
                    // next stage resident + all reads of current stage done:
                    // barrier covered by ks6/ks7 MMA work
                    if (ks == 6) {
                        CPA_WAIT(0);
                        __syncthreads();
                    }
                    // load ks0 fragments of NEXT stage, overlapping ks7 MMAs
                    if (ks == 7) {
#pragma unroll
                        for (int mi = 0; mi < 4; mi++)
                            LDSM4(afr[0][mi], pA + aBase + mi * 4096 + swzA[0]);
#pragma unroll
                        for (int g = 0; g < 4; g++)
                            LDSM4(bfr[0][g], pB + bBase + g * 4096 + swzB[0]);
                    }
                }

#pragma unroll
                for (int mi = 0; mi < 4; mi++) {
#pragma unroll
                    for (int nj = 0; nj < 8; nj++) {
                        mma16816(acc[mi][nj], afr[cur][mi],
                                 bfr[cur][nj >> 1][(nj & 1) * 2],
                                 bfr[cur][nj >> 1][(nj & 1) * 2 + 1]);
                    }
                }
            }
            buf ^= 1;
        }

        // ---------------- epilogue: scale + pre-quantized bias + relu ----------------
        // (next tile's stage0 is already loaded; its ks0 fragments are in slot 0)
        {
            int ctaM = (tile >> 5) * BM;
            int ctaN = (tile & 31) * BN;
            const float inv127 = 1.0f / 127.0f;
            int grow0 = ctaM + warp_m + (lane >> 2);
            int gcol0 = ctaN + warp_n + (lane & 3) * 2;

            float2 bq[8];
#pragma unroll
            for (int nj = 0; nj < 8; nj++)
                bq[nj] = *reinterpret_cast<const float2*>(g_bq + gcol0 + nj * 8);

#pragma unroll
            for (int mi = 0; mi < 4; mi++) {
#pragma unroll
                for (int h = 0; h < 2; h++) {
                    int grow = grow0 + mi * 16 + h * 8;
                    float* orow = out + (size_t)grow * N_DIM;
#pragma unroll
                    for (int nj = 0; nj < 8; nj++) {
                        float2 v;
                        v.x = fmaxf(fmaf(acc[mi][nj][h * 2 + 0], inv127, bq[nj].x), 0.0f);
                        v.y = fmaxf(fmaf(acc[mi][nj][h * 2 + 1], inv127, bq[nj].y), 0.0f);
                        *reinterpret_cast<float2*>(orow + gcol0 + nj * 8) = v;
                    }
                }
            }
        }

        if (!haveNext) break;
        tile = nextTile;
        gA = nA;
        gB = nB;
    }
}

// ---------------- launch ----------------
extern "C" void kernel_launch(void* const* d_in, const int* in_sizes, int n_in,
                              void* d_out, int out_size) {
    const float* x = (const float*)d_in[0];
    const float* w = (const float*)d_in[1];
    const float* bias = (const float*)d_in[2];
    float* out = (float*)d_out;

    cudaFuncSetAttribute(pwb_gemm_kernel,
                         cudaFuncAttributeMaxDynamicSharedMemorySize, SMEM_TOTAL);

    prep_kernel<<<XBLKS + WBLKS + BBLKS, 256>>>(x, w, bias);
    pwb_gemm_kernel<<<GRID_SMS, NTHREADS, SMEM_TOTAL>>>(out);
}